// round 4
// baseline (speedup 1.0000x reference)
#include <cuda_runtime.h>
#include <cstdint>

// SpecAugment: time-warp (±W shifted gather with zero borders) + freq mask + time mask.
// B=128, M=80, T=3000, W=80. Pure HBM-bound streaming rewrite.

namespace {
constexpr int B = 128;
constexpr int M = 80;
constexpr int T = 3000;
constexpr int W = 80;
constexpr int V = T / 4;            // 750 float4 groups per row
constexpr int TOTAL = B * M * V;    // 7,680,000 threads
}

__global__ void __launch_bounds__(256)
specaug_kernel(const float* __restrict__ spec,
               const int*   __restrict__ centers,
               const int*   __restrict__ fs_p,
               const int*   __restrict__ fw_p,
               const int*   __restrict__ ts_p,
               const int*   __restrict__ tw_p,
               float*       __restrict__ out)
{
    int gid = blockIdx.x * blockDim.x + threadIdx.x;
    if (gid >= TOTAL) return;

    int v  = gid % V;
    int bm = gid / V;
    int m  = bm % M;
    int b  = bm / M;
    int t0 = v * 4;

    float4* outv = reinterpret_cast<float4*>(out) + gid;

    // ---- frequency mask: whole row is zero -> write-only path (saves read BW)
    int f_start = __ldg(fs_p);
    int f_width = __ldg(fw_p);
    if (m >= f_start && m < f_start + f_width) {
        *outv = make_float4(0.f, 0.f, 0.f, 0.f);
        return;
    }

    int c = __ldg(&centers[b]);
    const float* row = spec + (size_t)bm * T;

    // ---- time warp gather (vectorized; W and T-W are multiples of 4, so the
    // zero-border regions cover whole float4 groups and shifted loads stay
    // 16B-aligned). Only the single group straddling c goes scalar.
    float4 val;
    if (t0 + 4 <= c) {
        int idx = t0 - W;                       // t < c  -> t - W
        val = (idx >= 0) ? *reinterpret_cast<const float4*>(row + idx)
                         : make_float4(0.f, 0.f, 0.f, 0.f);
    } else if (t0 >= c) {
        int idx = t0 + W;                       // t >= c -> t + W
        val = (idx + 4 <= T) ? *reinterpret_cast<const float4*>(row + idx)
                             : make_float4(0.f, 0.f, 0.f, 0.f);
    } else {
        float tmp[4];
        #pragma unroll
        for (int j = 0; j < 4; j++) {
            int t   = t0 + j;
            int idx = (t < c) ? t - W : t + W;
            tmp[j] = (idx >= 0 && idx < T) ? __ldg(row + idx) : 0.f;
        }
        val = make_float4(tmp[0], tmp[1], tmp[2], tmp[3]);
    }

    // ---- time mask: zero lanes with t in [t_start, t_start + t_width)
    int t_start = __ldg(ts_p);
    int t_end   = t_start + __ldg(tw_p);
    float* vp = reinterpret_cast<float*>(&val);
    #pragma unroll
    for (int j = 0; j < 4; j++) {
        int t = t0 + j;
        if (t >= t_start && t < t_end) vp[j] = 0.f;
    }

    *outv = val;
}

extern "C" void kernel_launch(void* const* d_in, const int* in_sizes, int n_in,
                              void* d_out, int out_size)
{
    const float* spec    = (const float*)d_in[0];
    const int*   centers = (const int*)  d_in[1];
    const int*   f_start = (const int*)  d_in[2];
    const int*   f_width = (const int*)  d_in[3];
    const int*   t_start = (const int*)  d_in[4];
    const int*   t_width = (const int*)  d_in[5];
    float*       out     = (float*)      d_out;

    const int threads = 256;
    const int blocks  = (TOTAL + threads - 1) / threads;  // 30000
    specaug_kernel<<<blocks, threads>>>(spec, centers, f_start, f_width,
                                        t_start, t_width, out);
}

// round 5
// speedup vs baseline: 1.0686x; 1.0686x over previous
#include <cuda_runtime.h>
#include <cstdint>

// SpecAugment: time-warp (±W shifted gather, zero borders) + freq mask + time mask.
// B=128, M=80, T=3000, W=80.
// One block per (b,m) row; 256 threads x 3 float4 groups = 768 >= 750 groups.
// Loads batched for MLP=3; index math hoisted to block scope.

namespace {
constexpr int B = 128;
constexpr int M = 80;
constexpr int T = 3000;
constexpr int W = 80;
constexpr int V = T / 4;        // 750 float4 groups per row
constexpr int THREADS = 256;
constexpr int K = 3;            // groups per thread
}

__global__ void __launch_bounds__(THREADS)
specaug_kernel(const float* __restrict__ spec,
               const int*   __restrict__ centers,
               const int*   __restrict__ fs_p,
               const int*   __restrict__ fw_p,
               const int*   __restrict__ ts_p,
               const int*   __restrict__ tw_p,
               float*       __restrict__ out)
{
    const int bm = blockIdx.x;          // row id in [0, B*M)
    const int b  = bm / M;
    const int m  = bm - b * M;

    float4* __restrict__ orow = reinterpret_cast<float4*>(out) + (size_t)bm * V;

    // ---- frequency mask: whole row zero -> write-only path (no reads)
    const int f_start = __ldg(fs_p);
    const int f_width = __ldg(fw_p);
    if (m >= f_start && m < f_start + f_width) {
        const float4 z = make_float4(0.f, 0.f, 0.f, 0.f);
        #pragma unroll
        for (int k = 0; k < K; k++) {
            int v = threadIdx.x + k * THREADS;
            if (v < V) orow[v] = z;
        }
        return;
    }

    const int c       = __ldg(centers + b);          // warp center, per-block broadcast
    const int t_start = __ldg(ts_p);
    const int t_end   = t_start + __ldg(tw_p);
    const float* __restrict__ row = spec + (size_t)bm * T;

    // ---- phase 1: batched gathers (3 independent LDG.128 per thread).
    // Common path is branch-free: select shifted index, predicate on bounds.
    // t0 and W are multiples of 4 -> shifted loads stay 16B aligned, and the
    // zero-border regions cover whole groups.
    float4 vals[K];
    #pragma unroll
    for (int k = 0; k < K; k++) {
        const int v   = threadIdx.x + k * THREADS;
        const int t0  = v * 4;
        const int idx = (t0 + 4 <= c) ? (t0 - W) : (t0 + W);
        const bool ok = (v < V) && (idx >= 0) && (idx + 4 <= T);
        vals[k] = ok ? *reinterpret_cast<const float4*>(row + idx)
                     : make_float4(0.f, 0.f, 0.f, 0.f);
    }

    // ---- phase 2: straddle fixup (at most one group per row), time mask, store
    #pragma unroll
    for (int k = 0; k < K; k++) {
        const int v = threadIdx.x + k * THREADS;
        if (v >= V) break;
        const int t0 = v * 4;
        float4 val = vals[k];
        float* vp = reinterpret_cast<float*>(&val);

        if (t0 < c && c < t0 + 4) {                  // group straddles the center
            #pragma unroll
            for (int j = 0; j < 4; j++) {
                const int t   = t0 + j;
                const int idx = (t < c) ? (t - W) : (t + W);
                vp[j] = (idx >= 0 && idx < T) ? __ldg(row + idx) : 0.f;
            }
        }

        #pragma unroll
        for (int j = 0; j < 4; j++) {
            const int t = t0 + j;
            if (t >= t_start && t < t_end) vp[j] = 0.f;
        }

        orow[v] = val;
    }
}

extern "C" void kernel_launch(void* const* d_in, const int* in_sizes, int n_in,
                              void* d_out, int out_size)
{
    const float* spec    = (const float*)d_in[0];
    const int*   centers = (const int*)  d_in[1];
    const int*   f_start = (const int*)  d_in[2];
    const int*   f_width = (const int*)  d_in[3];
    const int*   t_start = (const int*)  d_in[4];
    const int*   t_width = (const int*)  d_in[5];
    float*       out     = (float*)      d_out;

    specaug_kernel<<<B * M, THREADS>>>(spec, centers, f_start, f_width,
                                       t_start, t_width, out);
}